// round 16
// baseline (speedup 1.0000x reference)
#include <cuda_runtime.h>
#include <math.h>

#define Bb 8
#define Ss 1024
#define Dd 768
#define THETA 0.01f
#define NCTA 128
#define RPC 6
#define SCAN_T 1024

// ------------------------- scratch globals -------------------------
__device__ float g_k[Ss * Bb * Dd];     // [S][B][D]
__device__ float g_v[Ss * Bb * Dd];     // [S][B][D]
__device__ float g_q[Bb * Ss * Dd];     // [B,S,D] rows
__device__ float g_hid[Bb * Ss * Dd];
__device__ float g_alpha[Ss];
__device__ float g_eta[Ss];
__device__ float g_part[NCTA * Dd * Bb];  // per-CTA partial y, [cc][r*8+b]
__device__ float g_dy[Dd * Bb];           // dy, [r*8+b]
__device__ float g_W1f[Dd * Dd];
__device__ float g_W2f[Dd * Dd];
__device__ float g_b1f[Dd];
__device__ float g_b2f[Dd];
__device__ int g_flags[NCTA * 8];         // padded barrier flags (monotonic epochs)

// ------------------------- GEMM: C = act(A * W^T + bias) -------------------------
// 128x64 tile, 8x4 microtile, 256 threads. Strides are multiples of 4 so that
// row bases stay 16B-aligned for LDS.128 (130/66 would trap: misaligned address).
#define AS_STRIDE 132
#define WS_STRIDE 68
template <int ACT, int LAYOUT>
__global__ __launch_bounds__(256) void gemm_kernel(const float* __restrict__ A,
                                                   const float* __restrict__ W,
                                                   const float* __restrict__ bias,
                                                   float* __restrict__ C) {
    __shared__ float As[16 * AS_STRIDE];
    __shared__ float Ws[16 * WS_STRIDE];
    const int m0 = blockIdx.x * 128;
    const int n0 = blockIdx.y * 64;
    const int tid = threadIdx.x;
    const int tx = tid & 15;   // n: 4 cols each
    const int ty = tid >> 4;   // m: 8 rows each
    const int ar0 = tid >> 2;          // 0..63
    const int akc = (tid & 3) << 2;    // 0,4,8,12
    const int wr0 = tid >> 2;          // 0..63
    const int wkc = (tid & 3) << 2;

    float acc[8][4];
#pragma unroll
    for (int i = 0; i < 8; i++)
#pragma unroll
        for (int j = 0; j < 4; j++) acc[i][j] = 0.f;

    for (int k0 = 0; k0 < Dd; k0 += 16) {
        float4 a0 = *(const float4*)&A[(size_t)(m0 + ar0) * Dd + k0 + akc];
        float4 a1 = *(const float4*)&A[(size_t)(m0 + 64 + ar0) * Dd + k0 + akc];
        float4 wv = *(const float4*)&W[(size_t)(n0 + wr0) * Dd + k0 + wkc];
        __syncthreads();
        As[(akc + 0) * AS_STRIDE + ar0] = a0.x;
        As[(akc + 1) * AS_STRIDE + ar0] = a0.y;
        As[(akc + 2) * AS_STRIDE + ar0] = a0.z;
        As[(akc + 3) * AS_STRIDE + ar0] = a0.w;
        As[(akc + 0) * AS_STRIDE + 64 + ar0] = a1.x;
        As[(akc + 1) * AS_STRIDE + 64 + ar0] = a1.y;
        As[(akc + 2) * AS_STRIDE + 64 + ar0] = a1.z;
        As[(akc + 3) * AS_STRIDE + 64 + ar0] = a1.w;
        Ws[(wkc + 0) * WS_STRIDE + wr0] = wv.x;
        Ws[(wkc + 1) * WS_STRIDE + wr0] = wv.y;
        Ws[(wkc + 2) * WS_STRIDE + wr0] = wv.z;
        Ws[(wkc + 3) * WS_STRIDE + wr0] = wv.w;
        __syncthreads();
#pragma unroll
        for (int k = 0; k < 16; k++) {
            float4 av0 = *(const float4*)&As[k * AS_STRIDE + ty * 8];
            float4 av1 = *(const float4*)&As[k * AS_STRIDE + ty * 8 + 4];
            float4 w4 = *(const float4*)&Ws[k * WS_STRIDE + tx * 4];
            float ar[8] = {av0.x, av0.y, av0.z, av0.w, av1.x, av1.y, av1.z, av1.w};
            float wr[4] = {w4.x, w4.y, w4.z, w4.w};
#pragma unroll
            for (int i = 0; i < 8; i++)
#pragma unroll
                for (int j = 0; j < 4; j++) acc[i][j] = fmaf(ar[i], wr[j], acc[i][j]);
        }
    }

    float4 bv = *(const float4*)&bias[n0 + tx * 4];
#pragma unroll
    for (int i = 0; i < 8; i++) {
        int m = m0 + ty * 8 + i;
        size_t orow;
        if (LAYOUT == 0) {
            orow = (size_t)m * Dd;
        } else {
            int b = m >> 10;
            int s = m & 1023;
            orow = ((size_t)(s << 3) + b) * Dd;
        }
        float4 o;
        o.x = acc[i][0] + bv.x;
        o.y = acc[i][1] + bv.y;
        o.z = acc[i][2] + bv.z;
        o.w = acc[i][3] + bv.w;
        if (ACT) {
            o.x = o.x / (1.f + expf(-o.x));
            o.y = o.y / (1.f + expf(-o.y));
            o.z = o.z / (1.f + expf(-o.z));
            o.w = o.w / (1.f + expf(-o.w));
        }
        *(float4*)&C[orow + n0 + tx * 4] = o;
    }
}

// ------------------------- gates -------------------------
__global__ __launch_bounds__(256) void gates_kernel(const float* __restrict__ x,
    const float* __restrict__ FW1, const float* __restrict__ Fb1,
    const float* __restrict__ Fw2, const float* __restrict__ Fb2,
    const float* __restrict__ DW1, const float* __restrict__ Db1,
    const float* __restrict__ Dw2, const float* __restrict__ Db2,
    float* __restrict__ out_alpha, float* __restrict__ out_eta) {
    __shared__ float sx[8][768];
    __shared__ float swF[32][65];
    __shared__ float swD[32][65];
    __shared__ float sred[2][8][32];
    __shared__ float spart[2][8];
    const int s = blockIdx.x;
    const int tid = threadIdx.x;
    const int b = tid >> 5;
    const int g = tid & 31;

    for (int i = tid; i < 6144; i += 256) {
        int bb = i / 768, e = i - bb * 768;
        sx[bb][e] = x[((size_t)bb * 1024 + s) * 768 + e];
    }
    float aF = 0.f, aD = 0.f;
    for (int k0 = 0; k0 < 768; k0 += 64) {
        __syncthreads();
        for (int i = tid; i < 2048; i += 256) {
            int rr = i >> 6, cc = i & 63;
            swF[rr][cc] = FW1[rr * 768 + k0 + cc];
            swD[rr][cc] = DW1[rr * 768 + k0 + cc];
        }
        __syncthreads();
#pragma unroll 8
        for (int kk = 0; kk < 64; kk++) {
            float xv = sx[b][k0 + kk];
            aF += swF[g][kk] * xv;
            aD += swD[g][kk] * xv;
        }
    }
    aF += Fb1[g];
    aD += Db1[g];
    float hF = aF / (1.f + expf(-aF));
    float hD = aD / (1.f + expf(-aD));
    sred[0][b][g] = Fw2[g] * hF;
    sred[1][b][g] = Dw2[g] * hD;
    __syncthreads();
    if (tid < 16) {
        int which = tid >> 3, bb = tid & 7;
        float acc = which ? Db2[0] : Fb2[0];
#pragma unroll
        for (int gg = 0; gg < 32; gg++) acc += sred[which][bb][gg];
        spart[which][bb] = 1.f / (1.f + expf(-acc));
    }
    __syncthreads();
    if (tid == 0) {
        float m = 0.f;
#pragma unroll
        for (int bb = 0; bb < 8; bb++) m += spart[0][bb];
        out_alpha[s] = m * 0.125f;
    }
    if (tid == 1) {
        float m = 0.f;
#pragma unroll
        for (int bb = 0; bb < 8; bb++) m += spart[1][bb];
        out_eta[s] = m * 0.125f;
    }
}

// ------------------------- the sequential scan (R14 best family, unchanged) -------------------------
#define SCAN_SMEM_FLOATS 36112

__global__ __launch_bounds__(SCAN_T, 1) void scan_kernel(const float* __restrict__ MW1,
                                                         const float* __restrict__ Mb1,
                                                         const float* __restrict__ MW2,
                                                         const float* __restrict__ Mb2) {
    extern __shared__ float sm[];
    float* sW1   = sm;                  // [6][768]
    float* sS1   = sW1 + 4608;
    float* sW2T  = sS1 + 4608;          // [6][768] (columns of W2)
    float* sS2T  = sW2T + 4608;
    float* skt0  = sS2T + 4608;         // [2][768*9] double-buffered kt
    float* sred  = skt0 + 13824;        // [32][48]
    float* salpha = sred + 1536;        // [1024]
    float* seta  = salpha + 1024;       // [1024]
    float* sh1o  = seta + 1024;         // [48], 16B aligned
    float* svt   = sh1o + 48;
    float* sa1   = svt + 48;
    float* sda   = sa1 + 48;            // 16B aligned
    float* sdys  = sda + 48;
    float* sb1   = sdys + 48;           // [6]
    float* sSb1  = sb1 + 6;
    float* sb2   = sSb1 + 6;
    float* sSb2  = sb2 + 6;
    int*   sbase = (int*)(sSb2 + 6);

    const int tid = threadIdx.x;
    const int c = blockIdx.x;
    const int r0 = c * RPC;
    const int w = tid >> 5;
    const int l = tid & 31;
    const int bb = l >> 2;
    const int ks = l & 3;
    const int kbase = w * 24 + ks * 6;
    const int pb = tid >> 7;
    const int pe0 = (tid & 127) * 6;
    const int pgofs = pb * 768 + pe0;
    const int psmem = pe0 * 9 + pb;
    const int gq = tid / 48;            // 0..15
    const int gidx = tid - gq * 48;     // 0..47

    if (tid == 0) *sbase = *(volatile int*)&g_flags[c * 8];
    for (int i = tid; i < 4608; i += SCAN_T) {
        int rj = i / 768, d = i - rj * 768;
        sW1[i] = MW1[(r0 + rj) * 768 + d];
        sW2T[i] = MW2[d * 768 + r0 + rj];
        sS1[i] = 0.f;
        sS2T[i] = 0.f;
    }
    salpha[tid] = g_alpha[tid];
    seta[tid] = g_eta[tid];
    if (tid < 6) {
        sb1[tid] = Mb1[r0 + tid];
        sb2[tid] = Mb2[r0 + tid];
        sSb1[tid] = 0.f;
        sSb2[tid] = 0.f;
    }
    {
        const float* kt = g_k;
        float2 a0 = *(const float2*)(kt + pgofs + 0);
        float2 a1 = *(const float2*)(kt + pgofs + 2);
        float2 a2 = *(const float2*)(kt + pgofs + 4);
        skt0[psmem + 0] = a0.x; skt0[psmem + 9] = a0.y;
        skt0[psmem + 18] = a1.x; skt0[psmem + 27] = a1.y;
        skt0[psmem + 36] = a2.x; skt0[psmem + 45] = a2.y;
        if (tid < 48) svt[tid] = g_v[(tid & 7) * 768 + r0 + (tid >> 3)];
    }
    __syncthreads();
    const int base = *sbase;

    for (int t = 0; t < Ss; t++) {
        const float at = salpha[t];
        const float et = seta[t];
        const float ia = 1.f - at;
        float* skt = skt0 + (t & 1) * 6912;
        float* sktn = skt0 + ((t + 1) & 1) * 6912;

        // ---- P1: a1 = W1_owned @ kt ----
        {
            float kv0 = skt[(kbase + 0) * 9 + bb];
            float kv1 = skt[(kbase + 1) * 9 + bb];
            float kv2 = skt[(kbase + 2) * 9 + bb];
            float kv3 = skt[(kbase + 3) * 9 + bb];
            float kv4 = skt[(kbase + 4) * 9 + bb];
            float kv5 = skt[(kbase + 5) * 9 + bb];
            float acc[6];
#pragma unroll
            for (int r = 0; r < 6; r++) {
                const float* wr = &sW1[r * 768 + kbase];
                float2 w0 = *(const float2*)(wr + 0);
                float2 w1 = *(const float2*)(wr + 2);
                float2 w2 = *(const float2*)(wr + 4);
                float aA = w0.x * kv0;
                float aB = w0.y * kv1;
                aA = fmaf(w1.x, kv2, aA);
                aB = fmaf(w1.y, kv3, aB);
                aA = fmaf(w2.x, kv4, aA);
                aB = fmaf(w2.y, kv5, aB);
                acc[r] = aA + aB;
            }
#pragma unroll
            for (int r = 0; r < 6; r++) {
                acc[r] += __shfl_xor_sync(0xffffffffu, acc[r], 1);
                acc[r] += __shfl_xor_sync(0xffffffffu, acc[r], 2);
            }
            if (ks == 0) {
#pragma unroll
                for (int r = 0; r < 6; r++) sred[w * 48 + r * 8 + bb] = acc[r];
            }
        }
        __syncthreads();
        if (tid < 48) {
            float s0 = 0.f, s1 = 0.f, s2 = 0.f, s3 = 0.f;
#pragma unroll
            for (int ww = 0; ww < 8; ww++) {
                s0 += sred[(4 * ww + 0) * 48 + tid];
                s1 += sred[(4 * ww + 1) * 48 + tid];
                s2 += sred[(4 * ww + 2) * 48 + tid];
                s3 += sred[(4 * ww + 3) * 48 + tid];
            }
            float a1 = (s0 + s1) + (s2 + s3) + sb1[tid >> 3];
            sa1[tid] = a1;
            sh1o[tid] = a1 / (1.f + expf(-a1));
        }
        __syncthreads();

        // ---- prefetch kt(t+1), vt(t+1) ----
        float pk0, pk1, pk2, pk3, pk4, pk5;
        float pv = 0.f;
        {
            int tn = (t + 1 < Ss) ? t + 1 : t;
            const float* kn = g_k + tn * 6144;
            float2 a0 = __ldcg((const float2*)(kn + pgofs + 0));
            float2 a1 = __ldcg((const float2*)(kn + pgofs + 2));
            float2 a2 = __ldcg((const float2*)(kn + pgofs + 4));
            pk0 = a0.x; pk1 = a0.y; pk2 = a1.x;
            pk3 = a1.y; pk4 = a2.x; pk5 = a2.y;
            if (tid < 48)
                pv = __ldcg(&g_v[tn * 6144 + (tid & 7) * 768 + r0 + (tid >> 3)]);
        }

        // ---- P1b: partial y for row tid ----
        if (tid < 768) {
            float o[8];
#pragma unroll
            for (int b2 = 0; b2 < 8; b2++) o[b2] = 0.f;
#pragma unroll
            for (int ej = 0; ej < 6; ej++) {
                float wv = sW2T[ej * 768 + tid];
                float4 ha = *(const float4*)&sh1o[ej * 8];
                float4 hb = *(const float4*)&sh1o[ej * 8 + 4];
                o[0] = fmaf(wv, ha.x, o[0]);
                o[1] = fmaf(wv, ha.y, o[1]);
                o[2] = fmaf(wv, ha.z, o[2]);
                o[3] = fmaf(wv, ha.w, o[3]);
                o[4] = fmaf(wv, hb.x, o[4]);
                o[5] = fmaf(wv, hb.y, o[5]);
                o[6] = fmaf(wv, hb.z, o[6]);
                o[7] = fmaf(wv, hb.w, o[7]);
            }
            float4* dst = (float4*)&g_part[(size_t)c * 6144 + tid * 8];
            dst[0] = make_float4(o[0], o[1], o[2], o[3]);
            dst[1] = make_float4(o[4], o[5], o[6], o[7]);
        }
        // ---- barrier 1 ----
        __syncthreads();
        if (tid == 0) {
            asm volatile("st.release.gpu.global.s32 [%0], %1;"
                         :: "l"(&g_flags[c * 8]), "r"(base + 2 * t + 1) : "memory");
        }
        if (tid < NCTA) {
            int v;
            do {
                asm volatile("ld.acquire.gpu.global.s32 %0, [%1];"
                             : "=r"(v) : "l"(&g_flags[tid * 8]) : "memory");
            } while (v < base + 2 * t + 1);
        }
        __syncthreads();

        // ---- gather partial y, compute dy for owned rows ----
        if (tid < 768) {
            float a0 = 0.f, a1 = 0.f;
            const float* bp = g_part + (size_t)(gq * 8) * 6144 + r0 * 8 + gidx;
#pragma unroll
            for (int j = 0; j < 4; j++) {
                a0 += __ldcg(bp + (size_t)(2 * j) * 6144);
                a1 += __ldcg(bp + (size_t)(2 * j + 1) * 6144);
            }
            sred[gq * 48 + gidx] = a0 + a1;
        }
        __syncthreads();
        if (tid < 48) {
            float s0 = 0.f, s1 = 0.f, s2 = 0.f, s3 = 0.f;
#pragma unroll
            for (int q = 0; q < 4; q++) {
                s0 += sred[(4 * q + 0) * 48 + tid];
                s1 += sred[(4 * q + 1) * 48 + tid];
                s2 += sred[(4 * q + 2) * 48 + tid];
                s3 += sred[(4 * q + 3) * 48 + tid];
            }
            float y = (s0 + s1) + (s2 + s3);
            float dy = (y + sb2[tid >> 3] - svt[tid]) * (2.f / 6144.f);
            sdys[tid] = dy;
            g_dy[(r0 + (tid >> 3)) * 8 + (tid & 7)] = dy;
        }
        // ---- barrier 2 ----
        __syncthreads();
        if (tid == 0) {
            asm volatile("st.release.gpu.global.s32 [%0], %1;"
                         :: "l"(&g_flags[c * 8]), "r"(base + 2 * t + 2) : "memory");
        }
        if (tid < NCTA) {
            int v;
            do {
                asm volatile("ld.acquire.gpu.global.s32 %0, [%1];"
                             : "=r"(v) : "l"(&g_flags[tid * 8]) : "memory");
            } while (v < base + 2 * t + 2);
        }
        __syncthreads();

        // ---- P3: dh1 for owned units, dy read directly from g_dy ----
        {
            float dv0 = __ldcg(&g_dy[(kbase + 0) * 8 + bb]);
            float dv1 = __ldcg(&g_dy[(kbase + 1) * 8 + bb]);
            float dv2 = __ldcg(&g_dy[(kbase + 2) * 8 + bb]);
            float dv3 = __ldcg(&g_dy[(kbase + 3) * 8 + bb]);
            float dv4 = __ldcg(&g_dy[(kbase + 4) * 8 + bb]);
            float dv5 = __ldcg(&g_dy[(kbase + 5) * 8 + bb]);
            float acc[6];
#pragma unroll
            for (int r = 0; r < 6; r++) {
                const float* wr = &sW2T[r * 768 + kbase];
                float2 w0 = *(const float2*)(wr + 0);
                float2 w1 = *(const float2*)(wr + 2);
                float2 w2 = *(const float2*)(wr + 4);
                float aA = w0.x * dv0;
                float aB = w0.y * dv1;
                aA = fmaf(w1.x, dv2, aA);
                aB = fmaf(w1.y, dv3, aB);
                aA = fmaf(w2.x, dv4, aA);
                aB = fmaf(w2.y, dv5, aB);
                acc[r] = aA + aB;
            }
#pragma unroll
            for (int r = 0; r < 6; r++) {
                acc[r] += __shfl_xor_sync(0xffffffffu, acc[r], 1);
                acc[r] += __shfl_xor_sync(0xffffffffu, acc[r], 2);
            }
            if (ks == 0) {
#pragma unroll
                for (int r = 0; r < 6; r++) sred[w * 48 + r * 8 + bb] = acc[r];
            }
        }
        __syncthreads();
        if (tid < 48) {
            float s0 = 0.f, s1 = 0.f, s2 = 0.f, s3 = 0.f;
#pragma unroll
            for (int ww = 0; ww < 8; ww++) {
                s0 += sred[(4 * ww + 0) * 48 + tid];
                s1 += sred[(4 * ww + 1) * 48 + tid];
                s2 += sred[(4 * ww + 2) * 48 + tid];
                s3 += sred[(4 * ww + 3) * 48 + tid];
            }
            float s = (s0 + s1) + (s2 + s3);
            float a1 = sa1[tid];
            float sg = 1.f / (1.f + expf(-a1));
            float ds = sg * (1.f + a1 * (1.f - sg));
            sda[tid] = s * ds;
        }
        __syncthreads();
        if (tid < 6) {  // b1 + b2 updates
            float gs1 = 0.f, gs2 = 0.f;
#pragma unroll
            for (int b2i = 0; b2i < 8; b2i++) {
                gs1 += sda[tid * 8 + b2i];
                gs2 += sdys[tid * 8 + b2i];
            }
            float s1 = et * sSb1[tid] - THETA * gs1;
            sSb1[tid] = s1;
            sb1[tid] = fmaf(ia, sb1[tid], s1);
            float s2 = et * sSb2[tid] - THETA * gs2;
            sSb2[tid] = s2;
            sb2[tid] = fmaf(ia, sb2[tid], s2);
        }

        // ---- state updates + kt(t+1)/vt(t+1) commit into other buffer ----
        if (tid < 768) {
            const int d = tid;
            float kv8[8];
#pragma unroll
            for (int b2 = 0; b2 < 8; b2++) kv8[b2] = skt[d * 9 + b2];
            float4 yd0 = __ldcg((const float4*)&g_dy[d * 8]);
            float4 yd1 = __ldcg((const float4*)&g_dy[d * 8 + 4]);
#pragma unroll
            for (int r = 0; r < 6; r++) {
                float4 a0 = *(const float4*)&sda[r * 8];
                float4 a1 = *(const float4*)&sda[r * 8 + 4];
                float gA = a0.x * kv8[0];
                float gB = a0.y * kv8[1];
                gA = fmaf(a0.z, kv8[2], gA);
                gB = fmaf(a0.w, kv8[3], gB);
                gA = fmaf(a1.x, kv8[4], gA);
                gB = fmaf(a1.y, kv8[5], gB);
                gA = fmaf(a1.z, kv8[6], gA);
                gB = fmaf(a1.w, kv8[7], gB);
                float gr = gA + gB;
                int idx = r * 768 + d;
                float sv = fmaf(et, sS1[idx], -THETA * gr);
                sS1[idx] = sv;
                sW1[idx] = fmaf(ia, sW1[idx], sv);
            }
#pragma unroll
            for (int ej = 0; ej < 6; ej++) {
                float4 h0 = *(const float4*)&sh1o[ej * 8];
                float4 h1 = *(const float4*)&sh1o[ej * 8 + 4];
                float gA = h0.x * yd0.x;
                float gB = h0.y * yd0.y;
                gA = fmaf(h0.z, yd0.z, gA);
                gB = fmaf(h0.w, yd0.w, gB);
                gA = fmaf(h1.x, yd1.x, gA);
                gB = fmaf(h1.y, yd1.y, gB);
                gA = fmaf(h1.z, yd1.z, gA);
                gB = fmaf(h1.w, yd1.w, gB);
                float gr = gA + gB;
                int idx = ej * 768 + d;
                float sv = fmaf(et, sS2T[idx], -THETA * gr);
                sS2T[idx] = sv;
                sW2T[idx] = fmaf(ia, sW2T[idx], sv);
            }
        }
        sktn[psmem + 0] = pk0; sktn[psmem + 9] = pk1;
        sktn[psmem + 18] = pk2; sktn[psmem + 27] = pk3;
        sktn[psmem + 36] = pk4; sktn[psmem + 45] = pk5;
        if (tid < 48) svt[tid] = pv;
        __syncthreads();
    }

    // ---- export final state ----
    for (int i = tid; i < 4608; i += SCAN_T) {
        int rj = i / 768, d = i - rj * 768;
        g_W1f[(r0 + rj) * 768 + d] = sW1[i];
        g_W2f[d * 768 + (r0 + rj)] = sW2T[i];
    }
    if (tid < 6) {
        g_b1f[r0 + tid] = sb1[tid];
        g_b2f[r0 + tid] = sb2[tid];
    }
}

// ------------------------- launch -------------------------
extern "C" void kernel_launch(void* const* d_in, const int* in_sizes, int n_in,
                              void* d_out, int out_size) {
    const float* x   = (const float*)d_in[0];
    const float* WKw = (const float*)d_in[1];
    const float* WKb = (const float*)d_in[2];
    const float* WVw = (const float*)d_in[3];
    const float* WVb = (const float*)d_in[4];
    const float* WQw = (const float*)d_in[5];
    const float* WQb = (const float*)d_in[6];
    const float* MW1 = (const float*)d_in[7];
    const float* Mb1 = (const float*)d_in[8];
    const float* MW2 = (const float*)d_in[9];
    const float* Mb2 = (const float*)d_in[10];
    const float* FW1 = (const float*)d_in[11];
    const float* Fb1 = (const float*)d_in[12];
    const float* Fw2 = (const float*)d_in[13];
    const float* Fb2 = (const float*)d_in[14];
    const float* DW1 = (const float*)d_in[15];
    const float* Db1 = (const float*)d_in[16];
    const float* Dw2 = (const float*)d_in[17];
    const float* Db2 = (const float*)d_in[18];
    float* out = (float*)d_out;

    float *p_k, *p_v, *p_q, *p_hid, *p_alpha, *p_eta, *p_W1f, *p_W2f, *p_b1f, *p_b2f;
    cudaGetSymbolAddress((void**)&p_k, g_k);
    cudaGetSymbolAddress((void**)&p_v, g_v);
    cudaGetSymbolAddress((void**)&p_q, g_q);
    cudaGetSymbolAddress((void**)&p_hid, g_hid);
    cudaGetSymbolAddress((void**)&p_alpha, g_alpha);
    cudaGetSymbolAddress((void**)&p_eta, g_eta);
    cudaGetSymbolAddress((void**)&p_W1f, g_W1f);
    cudaGetSymbolAddress((void**)&p_W2f, g_W2f);
    cudaGetSymbolAddress((void**)&p_b1f, g_b1f);
    cudaGetSymbolAddress((void**)&p_b2f, g_b2f);

    cudaFuncSetAttribute(scan_kernel, cudaFuncAttributeMaxDynamicSharedMemorySize,
                         SCAN_SMEM_FLOATS * 4);

    dim3 gg(64, 12);   // 128x64 tiles over [8192, 768]
    // scan kept at launch index 3 (the slot ncu captures)
    gemm_kernel<0, 1><<<gg, 256>>>(x, WKw, WKb, p_k);                                      // 0
    gemm_kernel<0, 1><<<gg, 256>>>(x, WVw, WVb, p_v);                                      // 1
    gates_kernel<<<Ss, 256>>>(x, FW1, Fb1, Fw2, Fb2, DW1, Db1, Dw2, Db2, p_alpha, p_eta);  // 2
    scan_kernel<<<NCTA, SCAN_T, SCAN_SMEM_FLOATS * 4>>>(MW1, Mb1, MW2, Mb2);               // 3 <- profiled
    gemm_kernel<0, 0><<<gg, 256>>>(x, WQw, WQb, p_q);                                      // 4
    gemm_kernel<1, 0><<<gg, 256>>>(p_q, p_W1f, p_b1f, p_hid);                              // 5
    gemm_kernel<0, 0><<<gg, 256>>>(p_hid, p_W2f, p_b2f, out);                              // 6
}

// round 17
// speedup vs baseline: 1.0433x; 1.0433x over previous
#include <cuda_runtime.h>
#include <math.h>

#define Bb 8
#define Ss 1024
#define Dd 768
#define THETA 0.01f
#define NCTA 128
#define RPC 6
#define SCAN_T 1024

// ------------------------- scratch globals -------------------------
__device__ float g_k[Ss * Bb * Dd];     // [S][B][D]
__device__ float g_v[Ss * Bb * Dd];     // [S][B][D]
__device__ float g_q[Bb * Ss * Dd];     // [B,S,D] rows
__device__ float g_hid[Bb * Ss * Dd];
__device__ float g_alpha[Ss];
__device__ float g_eta[Ss];
__device__ float g_part[NCTA * Dd * Bb];  // per-CTA partial y, [cc][r*8+b]
__device__ float g_dy[Dd * Bb];           // dy, [r*8+b]
__device__ float g_W1f[Dd * Dd];
__device__ float g_W2f[Dd * Dd];
__device__ float g_b1f[Dd];
__device__ float g_b2f[Dd];
__device__ int g_flags[NCTA * 8];         // padded barrier flags (monotonic epochs)

// ------------------------- GEMM: C = act(A * W^T + bias) -------------------------
// 128x64 tile, 8x4 microtile, 256 threads. Strides multiple of 4 (16B-aligned rows).
#define AS_STRIDE 132
#define WS_STRIDE 68
template <int ACT, int LAYOUT>
__global__ __launch_bounds__(256) void gemm_kernel(const float* __restrict__ A,
                                                   const float* __restrict__ W,
                                                   const float* __restrict__ bias,
                                                   float* __restrict__ C) {
    __shared__ float As[16 * AS_STRIDE];
    __shared__ float Ws[16 * WS_STRIDE];
    const int m0 = blockIdx.x * 128;
    const int n0 = blockIdx.y * 64;
    const int tid = threadIdx.x;
    const int tx = tid & 15;   // n: 4 cols each
    const int ty = tid >> 4;   // m: 8 rows each
    const int ar0 = tid >> 2;          // 0..63
    const int akc = (tid & 3) << 2;    // 0,4,8,12
    const int wr0 = tid >> 2;          // 0..63
    const int wkc = (tid & 3) << 2;

    float acc[8][4];
#pragma unroll
    for (int i = 0; i < 8; i++)
#pragma unroll
        for (int j = 0; j < 4; j++) acc[i][j] = 0.f;

    for (int k0 = 0; k0 < Dd; k0 += 16) {
        float4 a0 = *(const float4*)&A[(size_t)(m0 + ar0) * Dd + k0 + akc];
        float4 a1 = *(const float4*)&A[(size_t)(m0 + 64 + ar0) * Dd + k0 + akc];
        float4 wv = *(const float4*)&W[(size_t)(n0 + wr0) * Dd + k0 + wkc];
        __syncthreads();
        As[(akc + 0) * AS_STRIDE + ar0] = a0.x;
        As[(akc + 1) * AS_STRIDE + ar0] = a0.y;
        As[(akc + 2) * AS_STRIDE + ar0] = a0.z;
        As[(akc + 3) * AS_STRIDE + ar0] = a0.w;
        As[(akc + 0) * AS_STRIDE + 64 + ar0] = a1.x;
        As[(akc + 1) * AS_STRIDE + 64 + ar0] = a1.y;
        As[(akc + 2) * AS_STRIDE + 64 + ar0] = a1.z;
        As[(akc + 3) * AS_STRIDE + 64 + ar0] = a1.w;
        Ws[(wkc + 0) * WS_STRIDE + wr0] = wv.x;
        Ws[(wkc + 1) * WS_STRIDE + wr0] = wv.y;
        Ws[(wkc + 2) * WS_STRIDE + wr0] = wv.z;
        Ws[(wkc + 3) * WS_STRIDE + wr0] = wv.w;
        __syncthreads();
#pragma unroll
        for (int k = 0; k < 16; k++) {
            float4 av0 = *(const float4*)&As[k * AS_STRIDE + ty * 8];
            float4 av1 = *(const float4*)&As[k * AS_STRIDE + ty * 8 + 4];
            float4 w4 = *(const float4*)&Ws[k * WS_STRIDE + tx * 4];
            float ar[8] = {av0.x, av0.y, av0.z, av0.w, av1.x, av1.y, av1.z, av1.w};
            float wr[4] = {w4.x, w4.y, w4.z, w4.w};
#pragma unroll
            for (int i = 0; i < 8; i++)
#pragma unroll
                for (int j = 0; j < 4; j++) acc[i][j] = fmaf(ar[i], wr[j], acc[i][j]);
        }
    }

    float4 bv = *(const float4*)&bias[n0 + tx * 4];
#pragma unroll
    for (int i = 0; i < 8; i++) {
        int m = m0 + ty * 8 + i;
        size_t orow;
        if (LAYOUT == 0) {
            orow = (size_t)m * Dd;
        } else {
            int b = m >> 10;
            int s = m & 1023;
            orow = ((size_t)(s << 3) + b) * Dd;
        }
        float4 o;
        o.x = acc[i][0] + bv.x;
        o.y = acc[i][1] + bv.y;
        o.z = acc[i][2] + bv.z;
        o.w = acc[i][3] + bv.w;
        if (ACT) {
            o.x = o.x / (1.f + expf(-o.x));
            o.y = o.y / (1.f + expf(-o.y));
            o.z = o.z / (1.f + expf(-o.z));
            o.w = o.w / (1.f + expf(-o.w));
        }
        *(float4*)&C[orow + n0 + tx * 4] = o;
    }
}

// ------------------------- gates -------------------------
__global__ __launch_bounds__(256) void gates_kernel(const float* __restrict__ x,
    const float* __restrict__ FW1, const float* __restrict__ Fb1,
    const float* __restrict__ Fw2, const float* __restrict__ Fb2,
    const float* __restrict__ DW1, const float* __restrict__ Db1,
    const float* __restrict__ Dw2, const float* __restrict__ Db2,
    float* __restrict__ out_alpha, float* __restrict__ out_eta) {
    __shared__ float sx[8][768];
    __shared__ float swF[32][65];
    __shared__ float swD[32][65];
    __shared__ float sred[2][8][32];
    __shared__ float spart[2][8];
    const int s = blockIdx.x;
    const int tid = threadIdx.x;
    const int b = tid >> 5;
    const int g = tid & 31;

    for (int i = tid; i < 6144; i += 256) {
        int bb = i / 768, e = i - bb * 768;
        sx[bb][e] = x[((size_t)bb * 1024 + s) * 768 + e];
    }
    float aF = 0.f, aD = 0.f;
    for (int k0 = 0; k0 < 768; k0 += 64) {
        __syncthreads();
        for (int i = tid; i < 2048; i += 256) {
            int rr = i >> 6, cc = i & 63;
            swF[rr][cc] = FW1[rr * 768 + k0 + cc];
            swD[rr][cc] = DW1[rr * 768 + k0 + cc];
        }
        __syncthreads();
#pragma unroll 8
        for (int kk = 0; kk < 64; kk++) {
            float xv = sx[b][k0 + kk];
            aF += swF[g][kk] * xv;
            aD += swD[g][kk] * xv;
        }
    }
    aF += Fb1[g];
    aD += Db1[g];
    float hF = aF / (1.f + expf(-aF));
    float hD = aD / (1.f + expf(-aD));
    sred[0][b][g] = Fw2[g] * hF;
    sred[1][b][g] = Dw2[g] * hD;
    __syncthreads();
    if (tid < 16) {
        int which = tid >> 3, bb = tid & 7;
        float acc = which ? Db2[0] : Fb2[0];
#pragma unroll
        for (int gg = 0; gg < 32; gg++) acc += sred[which][bb][gg];
        spart[which][bb] = 1.f / (1.f + expf(-acc));
    }
    __syncthreads();
    if (tid == 0) {
        float m = 0.f;
#pragma unroll
        for (int bb = 0; bb < 8; bb++) m += spart[0][bb];
        out_alpha[s] = m * 0.125f;
    }
    if (tid == 1) {
        float m = 0.f;
#pragma unroll
        for (int bb = 0; bb < 8; bb++) m += spart[1][bb];
        out_eta[s] = m * 0.125f;
    }
}

// ------------------------- the sequential scan (R11 champion, verbatim) -------------------------
#define SCAN_SMEM_FLOATS 36112

__global__ __launch_bounds__(SCAN_T, 1) void scan_kernel(const float* __restrict__ MW1,
                                                         const float* __restrict__ Mb1,
                                                         const float* __restrict__ MW2,
                                                         const float* __restrict__ Mb2) {
    extern __shared__ float sm[];
    float* sW1   = sm;                  // [6][768]
    float* sS1   = sW1 + 4608;
    float* sW2T  = sS1 + 4608;          // [6][768] (columns of W2)
    float* sS2T  = sW2T + 4608;
    float* skt   = sS2T + 4608;         // [768][9 pad]
    float* sdy   = skt + 6912;          // [768][9 pad]
    float* sred  = sdy + 6912;          // [32][48]
    float* salpha = sred + 1536;        // [1024]
    float* seta  = salpha + 1024;       // [1024]
    float* sh1o  = seta + 1024;         // [48], 16B aligned
    float* svt   = sh1o + 48;
    float* sa1   = svt + 48;
    float* sda   = sa1 + 48;            // 16B aligned
    float* sdys  = sda + 48;
    float* sb1   = sdys + 48;           // [6]
    float* sSb1  = sb1 + 6;
    float* sb2   = sSb1 + 6;
    float* sSb2  = sb2 + 6;
    int*   sbase = (int*)(sSb2 + 6);

    const int tid = threadIdx.x;
    const int c = blockIdx.x;
    const int r0 = c * RPC;
    const int w = tid >> 5;
    const int l = tid & 31;
    const int bb = l >> 2;
    const int ks = l & 3;
    const int kbase = w * 24 + ks * 6;
    const int pb = tid >> 7;
    const int pe0 = (tid & 127) * 6;
    const int pgofs = pb * 768 + pe0;
    const int psmem = pe0 * 9 + pb;
    const int gq = tid / 48;            // 0..15
    const int gidx = tid - gq * 48;     // 0..47

    if (tid == 0) *sbase = *(volatile int*)&g_flags[c * 8];
    for (int i = tid; i < 4608; i += SCAN_T) {
        int rj = i / 768, d = i - rj * 768;
        sW1[i] = MW1[(r0 + rj) * 768 + d];
        sW2T[i] = MW2[d * 768 + r0 + rj];
        sS1[i] = 0.f;
        sS2T[i] = 0.f;
    }
    salpha[tid] = g_alpha[tid];
    seta[tid] = g_eta[tid];
    if (tid < 6) {
        sb1[tid] = Mb1[r0 + tid];
        sb2[tid] = Mb2[r0 + tid];
        sSb1[tid] = 0.f;
        sSb2[tid] = 0.f;
    }
    {
        const float* kt = g_k;
        float2 a0 = *(const float2*)(kt + pgofs + 0);
        float2 a1 = *(const float2*)(kt + pgofs + 2);
        float2 a2 = *(const float2*)(kt + pgofs + 4);
        skt[psmem + 0] = a0.x; skt[psmem + 9] = a0.y;
        skt[psmem + 18] = a1.x; skt[psmem + 27] = a1.y;
        skt[psmem + 36] = a2.x; skt[psmem + 45] = a2.y;
        if (tid < 48) svt[tid] = g_v[(tid & 7) * 768 + r0 + (tid >> 3)];
    }
    __syncthreads();
    const int base = *sbase;

    for (int t = 0; t < Ss; t++) {
        const float at = salpha[t];
        const float et = seta[t];
        const float ia = 1.f - at;

        // ---- P1: a1 = W1_owned @ kt (split-k over 32 warps, 6 k per lane) ----
        {
            float kv0 = skt[(kbase + 0) * 9 + bb];
            float kv1 = skt[(kbase + 1) * 9 + bb];
            float kv2 = skt[(kbase + 2) * 9 + bb];
            float kv3 = skt[(kbase + 3) * 9 + bb];
            float kv4 = skt[(kbase + 4) * 9 + bb];
            float kv5 = skt[(kbase + 5) * 9 + bb];
            float acc[6];
#pragma unroll
            for (int r = 0; r < 6; r++) {
                const float* wr = &sW1[r * 768 + kbase];
                float2 w0 = *(const float2*)(wr + 0);
                float2 w1 = *(const float2*)(wr + 2);
                float2 w2 = *(const float2*)(wr + 4);
                float aA = w0.x * kv0;
                float aB = w0.y * kv1;
                aA = fmaf(w1.x, kv2, aA);
                aB = fmaf(w1.y, kv3, aB);
                aA = fmaf(w2.x, kv4, aA);
                aB = fmaf(w2.y, kv5, aB);
                acc[r] = aA + aB;
            }
#pragma unroll
            for (int r = 0; r < 6; r++) {
                acc[r] += __shfl_xor_sync(0xffffffffu, acc[r], 1);
                acc[r] += __shfl_xor_sync(0xffffffffu, acc[r], 2);
            }
            if (ks == 0) {
#pragma unroll
                for (int r = 0; r < 6; r++) sred[w * 48 + r * 8 + bb] = acc[r];
            }
        }
        __syncthreads();
        if (tid < 48) {
            float s0 = 0.f, s1 = 0.f, s2 = 0.f, s3 = 0.f;
#pragma unroll
            for (int ww = 0; ww < 8; ww++) {
                s0 += sred[(4 * ww + 0) * 48 + tid];
                s1 += sred[(4 * ww + 1) * 48 + tid];
                s2 += sred[(4 * ww + 2) * 48 + tid];
                s3 += sred[(4 * ww + 3) * 48 + tid];
            }
            float a1 = (s0 + s1) + (s2 + s3) + sb1[tid >> 3];
            sa1[tid] = a1;
            sh1o[tid] = a1 / (1.f + expf(-a1));
        }
        __syncthreads();

        // ---- prefetch kt(t+1), vt(t+1) into registers ----
        float pk0, pk1, pk2, pk3, pk4, pk5;
        float pv = 0.f;
        {
            int tn = (t + 1 < Ss) ? t + 1 : t;
            const float* kn = g_k + tn * 6144;
            float2 a0 = __ldcg((const float2*)(kn + pgofs + 0));
            float2 a1 = __ldcg((const float2*)(kn + pgofs + 2));
            float2 a2 = __ldcg((const float2*)(kn + pgofs + 4));
            pk0 = a0.x; pk1 = a0.y; pk2 = a1.x;
            pk3 = a1.y; pk4 = a2.x; pk5 = a2.y;
            if (tid < 48)
                pv = __ldcg(&g_v[tn * 6144 + (tid & 7) * 768 + r0 + (tid >> 3)]);
        }

        // ---- P1b: partial y for row tid (ej-outer) ----
        if (tid < 768) {
            float o[8];
#pragma unroll
            for (int b2 = 0; b2 < 8; b2++) o[b2] = 0.f;
#pragma unroll
            for (int ej = 0; ej < 6; ej++) {
                float wv = sW2T[ej * 768 + tid];
                float4 ha = *(const float4*)&sh1o[ej * 8];
                float4 hb = *(const float4*)&sh1o[ej * 8 + 4];
                o[0] = fmaf(wv, ha.x, o[0]);
                o[1] = fmaf(wv, ha.y, o[1]);
                o[2] = fmaf(wv, ha.z, o[2]);
                o[3] = fmaf(wv, ha.w, o[3]);
                o[4] = fmaf(wv, hb.x, o[4]);
                o[5] = fmaf(wv, hb.y, o[5]);
                o[6] = fmaf(wv, hb.z, o[6]);
                o[7] = fmaf(wv, hb.w, o[7]);
            }
            float4* dst = (float4*)&g_part[(size_t)c * 6144 + tid * 8];
            dst[0] = make_float4(o[0], o[1], o[2], o[3]);
            dst[1] = make_float4(o[4], o[5], o[6], o[7]);
        }
        // ---- barrier 1 ----
        __syncthreads();
        if (tid == 0) {
            asm volatile("st.release.gpu.global.s32 [%0], %1;"
                         :: "l"(&g_flags[c * 8]), "r"(base + 2 * t + 1) : "memory");
        }
        if (tid < NCTA) {
            int v;
            do {
                asm volatile("ld.acquire.gpu.global.s32 %0, [%1];"
                             : "=r"(v) : "l"(&g_flags[tid * 8]) : "memory");
            } while (v < base + 2 * t + 1);
        }
        __syncthreads();

        // ---- gather partial y, compute dy for owned rows ----
        if (tid < 768) {
            float a0 = 0.f, a1 = 0.f;
            const float* bp = g_part + (size_t)(gq * 8) * 6144 + r0 * 8 + gidx;
#pragma unroll
            for (int j = 0; j < 4; j++) {
                a0 += __ldcg(bp + (size_t)(2 * j) * 6144);
                a1 += __ldcg(bp + (size_t)(2 * j + 1) * 6144);
            }
            sred[gq * 48 + gidx] = a0 + a1;
        }
        __syncthreads();
        if (tid < 48) {
            float s0 = 0.f, s1 = 0.f, s2 = 0.f, s3 = 0.f;
#pragma unroll
            for (int q = 0; q < 4; q++) {
                s0 += sred[(4 * q + 0) * 48 + tid];
                s1 += sred[(4 * q + 1) * 48 + tid];
                s2 += sred[(4 * q + 2) * 48 + tid];
                s3 += sred[(4 * q + 3) * 48 + tid];
            }
            float y = (s0 + s1) + (s2 + s3);
            float dy = (y + sb2[tid >> 3] - svt[tid]) * (2.f / 6144.f);
            sdys[tid] = dy;
            g_dy[(r0 + (tid >> 3)) * 8 + (tid & 7)] = dy;
        }
        // ---- barrier 2 ----
        __syncthreads();
        if (tid == 0) {
            asm volatile("st.release.gpu.global.s32 [%0], %1;"
                         :: "l"(&g_flags[c * 8]), "r"(base + 2 * t + 2) : "memory");
        }
        if (tid < NCTA) {
            int v;
            do {
                asm volatile("ld.acquire.gpu.global.s32 %0, [%1];"
                             : "=r"(v) : "l"(&g_flags[tid * 8]) : "memory");
            } while (v < base + 2 * t + 2);
        }
        __syncthreads();

        // ---- stage dy transposed: thread tid<768 handles its row ----
        if (tid < 768) {
            const float4* src = (const float4*)&g_dy[tid * 8];
            float4 d0 = __ldcg(src + 0);
            float4 d1 = __ldcg(src + 1);
            float* p0 = &sdy[tid * 9];
            p0[0] = d0.x; p0[1] = d0.y; p0[2] = d0.z; p0[3] = d0.w;
            p0[4] = d1.x; p0[5] = d1.y; p0[6] = d1.z; p0[7] = d1.w;
        }
        __syncthreads();

        // ---- P3: dh1 for owned units (split-k over 32 warps) ----
        {
            float dv0 = sdy[(kbase + 0) * 9 + bb];
            float dv1 = sdy[(kbase + 1) * 9 + bb];
            float dv2 = sdy[(kbase + 2) * 9 + bb];
            float dv3 = sdy[(kbase + 3) * 9 + bb];
            float dv4 = sdy[(kbase + 4) * 9 + bb];
            float dv5 = sdy[(kbase + 5) * 9 + bb];
            float acc[6];
#pragma unroll
            for (int r = 0; r < 6; r++) {
                const float* wr = &sW2T[r * 768 + kbase];
                float2 w0 = *(const float2*)(wr + 0);
                float2 w1 = *(const float2*)(wr + 2);
                float2 w2 = *(const float2*)(wr + 4);
                float aA = w0.x * dv0;
                float aB = w0.y * dv1;
                aA = fmaf(w1.x, dv2, aA);
                aB = fmaf(w1.y, dv3, aB);
                aA = fmaf(w2.x, dv4, aA);
                aB = fmaf(w2.y, dv5, aB);
                acc[r] = aA + aB;
            }
#pragma unroll
            for (int r = 0; r < 6; r++) {
                acc[r] += __shfl_xor_sync(0xffffffffu, acc[r], 1);
                acc[r] += __shfl_xor_sync(0xffffffffu, acc[r], 2);
            }
            if (ks == 0) {
#pragma unroll
                for (int r = 0; r < 6; r++) sred[w * 48 + r * 8 + bb] = acc[r];
            }
        }
        __syncthreads();
        if (tid < 48) {
            float s0 = 0.f, s1 = 0.f, s2 = 0.f, s3 = 0.f;
#pragma unroll
            for (int ww = 0; ww < 8; ww++) {
                s0 += sred[(4 * ww + 0) * 48 + tid];
                s1 += sred[(4 * ww + 1) * 48 + tid];
                s2 += sred[(4 * ww + 2) * 48 + tid];
                s3 += sred[(4 * ww + 3) * 48 + tid];
            }
            float s = (s0 + s1) + (s2 + s3);
            float a1 = sa1[tid];
            float sg = 1.f / (1.f + expf(-a1));
            float ds = sg * (1.f + a1 * (1.f - sg));
            sda[tid] = s * ds;
        }
        __syncthreads();
        if (tid < 6) {  // b1 + b2 updates
            float gs1 = 0.f, gs2 = 0.f;
#pragma unroll
            for (int b2i = 0; b2i < 8; b2i++) {
                gs1 += sda[tid * 8 + b2i];
                gs2 += sdys[tid * 8 + b2i];
            }
            float s1 = et * sSb1[tid] - THETA * gs1;
            sSb1[tid] = s1;
            sb1[tid] = fmaf(ia, sb1[tid], s1);
            float s2 = et * sSb2[tid] - THETA * gs2;
            sSb2[tid] = s2;
            sb2[tid] = fmaf(ia, sb2[tid], s2);
        }

        // ---- state updates (streaming, no big register arrays) ----
        if (tid < 768) {
            const int d = tid;
            float kv8[8], y8[8];
#pragma unroll
            for (int b2 = 0; b2 < 8; b2++) {
                kv8[b2] = skt[d * 9 + b2];
                y8[b2] = sdy[d * 9 + b2];
            }
#pragma unroll
            for (int r = 0; r < 6; r++) {
                float4 a0 = *(const float4*)&sda[r * 8];
                float4 a1 = *(const float4*)&sda[r * 8 + 4];
                float gA = a0.x * kv8[0];
                float gB = a0.y * kv8[1];
                gA = fmaf(a0.z, kv8[2], gA);
                gB = fmaf(a0.w, kv8[3], gB);
                gA = fmaf(a1.x, kv8[4], gA);
                gB = fmaf(a1.y, kv8[5], gB);
                gA = fmaf(a1.z, kv8[6], gA);
                gB = fmaf(a1.w, kv8[7], gB);
                float gr = gA + gB;
                int idx = r * 768 + d;
                float sv = fmaf(et, sS1[idx], -THETA * gr);
                sS1[idx] = sv;
                sW1[idx] = fmaf(ia, sW1[idx], sv);
            }
#pragma unroll
            for (int ej = 0; ej < 6; ej++) {
                float4 h0 = *(const float4*)&sh1o[ej * 8];
                float4 h1 = *(const float4*)&sh1o[ej * 8 + 4];
                float gA = h0.x * y8[0];
                float gB = h0.y * y8[1];
                gA = fmaf(h0.z, y8[2], gA);
                gB = fmaf(h0.w, y8[3], gB);
                gA = fmaf(h1.x, y8[4], gA);
                gB = fmaf(h1.y, y8[5], gB);
                gA = fmaf(h1.z, y8[6], gA);
                gB = fmaf(h1.w, y8[7], gB);
                float gr = gA + gB;
                int idx = ej * 768 + d;
                float sv = fmaf(et, sS2T[idx], -THETA * gr);
                sS2T[idx] = sv;
                sW2T[idx] = fmaf(ia, sW2T[idx], sv);
            }
        }
        __syncthreads();  // updates done reading skt/sdy

        // ---- commit prefetched kt(t+1), vt(t+1) ----
        skt[psmem + 0] = pk0; skt[psmem + 9] = pk1;
        skt[psmem + 18] = pk2; skt[psmem + 27] = pk3;
        skt[psmem + 36] = pk4; skt[psmem + 45] = pk5;
        if (tid < 48) svt[tid] = pv;
        __syncthreads();
    }

    // ---- export final state ----
    for (int i = tid; i < 4608; i += SCAN_T) {
        int rj = i / 768, d = i - rj * 768;
        g_W1f[(r0 + rj) * 768 + d] = sW1[i];
        g_W2f[d * 768 + (r0 + rj)] = sW2T[i];
    }
    if (tid < 6) {
        g_b1f[r0 + tid] = sb1[tid];
        g_b2f[r0 + tid] = sb2[tid];
    }
}

// ------------------------- launch -------------------------
extern "C" void kernel_launch(void* const* d_in, const int* in_sizes, int n_in,
                              void* d_out, int out_size) {
    const float* x   = (const float*)d_in[0];
    const float* WKw = (const float*)d_in[1];
    const float* WKb = (const float*)d_in[2];
    const float* WVw = (const float*)d_in[3];
    const float* WVb = (const float*)d_in[4];
    const float* WQw = (const float*)d_in[5];
    const float* WQb = (const float*)d_in[6];
    const float* MW1 = (const float*)d_in[7];
    const float* Mb1 = (const float*)d_in[8];
    const float* MW2 = (const float*)d_in[9];
    const float* Mb2 = (const float*)d_in[10];
    const float* FW1 = (const float*)d_in[11];
    const float* Fb1 = (const float*)d_in[12];
    const float* Fw2 = (const float*)d_in[13];
    const float* Fb2 = (const float*)d_in[14];
    const float* DW1 = (const float*)d_in[15];
    const float* Db1 = (const float*)d_in[16];
    const float* Dw2 = (const float*)d_in[17];
    const float* Db2 = (const float*)d_in[18];
    float* out = (float*)d_out;

    float *p_k, *p_v, *p_q, *p_hid, *p_alpha, *p_eta, *p_W1f, *p_W2f, *p_b1f, *p_b2f;
    cudaGetSymbolAddress((void**)&p_k, g_k);
    cudaGetSymbolAddress((void**)&p_v, g_v);
    cudaGetSymbolAddress((void**)&p_q, g_q);
    cudaGetSymbolAddress((void**)&p_hid, g_hid);
    cudaGetSymbolAddress((void**)&p_alpha, g_alpha);
    cudaGetSymbolAddress((void**)&p_eta, g_eta);
    cudaGetSymbolAddress((void**)&p_W1f, g_W1f);
    cudaGetSymbolAddress((void**)&p_W2f, g_W2f);
    cudaGetSymbolAddress((void**)&p_b1f, g_b1f);
    cudaGetSymbolAddress((void**)&p_b2f, g_b2f);

    cudaFuncSetAttribute(scan_kernel, cudaFuncAttributeMaxDynamicSharedMemorySize,
                         SCAN_SMEM_FLOATS * 4);

    dim3 gg(64, 12);   // 128x64 tiles over [8192, 768]
    // scan kept at launch index 3 (the slot ncu captures)
    gemm_kernel<0, 1><<<gg, 256>>>(x, WKw, WKb, p_k);                                      // 0
    gemm_kernel<0, 1><<<gg, 256>>>(x, WVw, WVb, p_v);                                      // 1
    gates_kernel<<<Ss, 256>>>(x, FW1, Fb1, Fw2, Fb2, DW1, Db1, Dw2, Db2, p_alpha, p_eta);  // 2
    scan_kernel<<<NCTA, SCAN_T, SCAN_SMEM_FLOATS * 4>>>(MW1, Mb1, MW2, Mb2);               // 3 <- profiled
    gemm_kernel<0, 0><<<gg, 256>>>(x, WQw, WQb, p_q);                                      // 4
    gemm_kernel<1, 0><<<gg, 256>>>(p_q, p_W1f, p_b1f, p_hid);                              // 5
    gemm_kernel<0, 0><<<gg, 256>>>(p_hid, p_W2f, p_b2f, out);                              // 6
}